// round 6
// baseline (speedup 1.0000x reference)
#include <cuda_runtime.h>
#include <cstdint>

// Problem constants (shapes fixed by the dataset)
#define MAX_N 100000
#define MAX_E 640000
#define DIM   128

// Per-node accumulators consumed by the GEMM:
//   g_xacc[n][0:128]   = sum over edges (dst==n) of w_e * x[src_e]
//   g_xacc[n][128:256] = sum over edges (dst==n) of w_e * edge_attr_e
//   g_s[n]             = sum over edges (dst==n) of w_e
__device__ float g_xacc[(size_t)MAX_N * 256];
__device__ float g_s[MAX_N];

// CSR scratch. Triple packed: {src, w_bits, eid, 0} -> one LDG.128 per edge.
__device__ int  g_count[MAX_N];
__device__ int  g_off[MAX_N];
__device__ int  g_cursor[MAX_N];
__device__ int  g_bsum[128];
__device__ int4 g_csr[MAX_E];

// ---------------------------------------------------------------------------
// CSR build: zero counts -> histogram -> exclusive scan -> scatter triples
// ---------------------------------------------------------------------------
__global__ void zero_counts(int N)
{
    int i = blockIdx.x * blockDim.x + threadIdx.x;
    if (i < N) g_count[i] = 0;
}

__global__ void hist_kernel(const int* __restrict__ dst, int E)
{
    int i = blockIdx.x * blockDim.x + threadIdx.x;
    if (i < E) atomicAdd(&g_count[dst[i]], 1);
}

#define SCAN_B 1024
__global__ __launch_bounds__(SCAN_B)
void scan_block(int N)
{
    __shared__ int sh[SCAN_B];
    int i = blockIdx.x * SCAN_B + threadIdx.x;
    int v = (i < N) ? g_count[i] : 0;
    sh[threadIdx.x] = v;
    __syncthreads();
    for (int off = 1; off < SCAN_B; off <<= 1) {
        int t = (threadIdx.x >= off) ? sh[threadIdx.x - off] : 0;
        __syncthreads();
        sh[threadIdx.x] += t;
        __syncthreads();
    }
    int incl = sh[threadIdx.x];
    if (i < N) g_off[i] = incl - v;           // exclusive within block
    if (threadIdx.x == SCAN_B - 1) g_bsum[blockIdx.x] = incl;
}

__global__ __launch_bounds__(128)
void scan_sums(int nb)
{
    __shared__ int sh[128];
    int v = (threadIdx.x < nb) ? g_bsum[threadIdx.x] : 0;
    sh[threadIdx.x] = v;
    __syncthreads();
    for (int off = 1; off < 128; off <<= 1) {
        int t = (threadIdx.x >= off) ? sh[threadIdx.x - off] : 0;
        __syncthreads();
        sh[threadIdx.x] += t;
        __syncthreads();
    }
    if (threadIdx.x < nb) g_bsum[threadIdx.x] = sh[threadIdx.x] - v;  // exclusive
}

__global__ __launch_bounds__(SCAN_B)
void scan_add(int N)
{
    int i = blockIdx.x * SCAN_B + threadIdx.x;
    if (i < N) {
        int o = g_off[i] + g_bsum[blockIdx.x];
        g_off[i]    = o;
        g_cursor[i] = o;
    }
}

__global__ void scatter_kernel(const int* __restrict__ src,
                               const int* __restrict__ dst,
                               const float* __restrict__ ew,
                               int E)
{
    int e = blockIdx.x * blockDim.x + threadIdx.x;
    if (e < E) {
        int d   = dst[e];
        int pos = atomicAdd(&g_cursor[d], 1);
        g_csr[pos] = make_int4(src[e], __float_as_int(ew[e]), e, 0);
    }
}

// ---------------------------------------------------------------------------
// Gather pass: one warp per node. Fully predicated 8-wide edge rounds:
// load 8 clamped triples, issue all 16 row gathers, accumulate with
// zeroed weights for out-of-range edges. Most nodes (deg<=8) take exactly
// ONE memory round; clamped duplicates hit L1.
// ---------------------------------------------------------------------------
__global__ __launch_bounds__(256, 2)
void gather_kernel(const float* __restrict__ x,
                   const float* __restrict__ ea,
                   int N)
{
    const int lane   = threadIdx.x & 31;
    const int warp0  = (int)((blockIdx.x * blockDim.x + threadIdx.x) >> 5);
    const int nwarps = (int)((gridDim.x * blockDim.x) >> 5);

    for (int n = warp0; n < N; n += nwarps) {
        const int start = g_off[n];
        const int deg   = g_count[n];

        float4 ax = make_float4(0.f, 0.f, 0.f, 0.f);
        float4 aE = make_float4(0.f, 0.f, 0.f, 0.f);
        float  ws = 0.f;

        for (int j0 = 0; j0 < deg; j0 += 8) {
            int4  t[8];
            float w[8];
            #pragma unroll
            for (int u = 0; u < 8; u++) {
                int jj = j0 + u;
                int jc = (jj < deg) ? jj : (deg - 1);
                t[u] = __ldg(g_csr + start + jc);
                w[u] = (jj < deg) ? __int_as_float(t[u].y) : 0.f;
            }
            float4 xv[8], ev[8];
            #pragma unroll
            for (int u = 0; u < 8; u++)
                xv[u] = __ldg((const float4*)(x + (size_t)t[u].x * DIM) + lane);
            #pragma unroll
            for (int u = 0; u < 8; u++)
                ev[u] = __ldg((const float4*)(ea + (size_t)t[u].z * DIM) + lane);

            #pragma unroll
            for (int u = 0; u < 8; u++) {
                ax.x += w[u] * xv[u].x; ax.y += w[u] * xv[u].y;
                ax.z += w[u] * xv[u].z; ax.w += w[u] * xv[u].w;
            }
            #pragma unroll
            for (int u = 0; u < 8; u++) {
                aE.x += w[u] * ev[u].x; aE.y += w[u] * ev[u].y;
                aE.z += w[u] * ev[u].z; aE.w += w[u] * ev[u].w;
            }
            #pragma unroll
            for (int u = 0; u < 8; u++)
                ws += w[u];
        }

        float* base = g_xacc + (size_t)n * 256 + lane * 4;
        *(float4*)(base)       = ax;
        *(float4*)(base + 128) = aE;
        if (lane == 0) g_s[n] = ws;
    }
}

// ---------------------------------------------------------------------------
// tf32 tensor-core GEMM:  out[N,128] = A_virtual[N,512] @ Bcat[512,128]
//   A k-regions:   [0,128)  : x * s[row]      (stride 128)
//                  [128,384): g_xacc          (stride 256)
//                  [384,512): x               (stride 128)
//   B k-regions:   [0,384)  : W_msg rows; [384,512): W_self rows
// ---------------------------------------------------------------------------
#define GBM 128
#define GBK 32
#define A_STRIDE 36
#define B_STRIDE 136

__device__ __forceinline__ uint32_t f2tf32(float f)
{
    uint32_t u;
    asm("cvt.rna.tf32.f32 %0, %1;" : "=r"(u) : "f"(f));
    return u;
}

__device__ __forceinline__ void mma_tf32(float c[4], const uint32_t a[4], const uint32_t b[2])
{
    asm("mma.sync.aligned.m16n8k8.row.col.f32.tf32.tf32.f32 "
        "{%0,%1,%2,%3}, {%4,%5,%6,%7}, {%8,%9}, {%0,%1,%2,%3};"
        : "+f"(c[0]), "+f"(c[1]), "+f"(c[2]), "+f"(c[3])
        : "r"(a[0]), "r"(a[1]), "r"(a[2]), "r"(a[3]), "r"(b[0]), "r"(b[1]));
}

__global__ __launch_bounds__(256)
void gemm_tf32_kernel(const float* __restrict__ x,
                      const float* __restrict__ Wmsg,
                      const float* __restrict__ Wself,
                      float* __restrict__ out,
                      int N)
{
    __shared__ uint32_t As[GBM * A_STRIDE];   // [m][k], tf32 bits
    __shared__ uint32_t Bs[GBK * B_STRIDE];   // [k][n], tf32 bits

    const int tid   = threadIdx.x;
    const int lane  = tid & 31;
    const int warp  = tid >> 5;
    const int warpM = warp & 1;     // 0..1
    const int warpN = warp >> 1;    // 0..3
    const int g     = lane >> 2;    // groupID 0..7
    const int t     = lane & 3;     // threadID_in_group 0..3

    const int row0 = blockIdx.x * GBM;

    float acc[4][4][4];
    #pragma unroll
    for (int mt = 0; mt < 4; mt++)
        #pragma unroll
        for (int nt = 0; nt < 4; nt++)
            #pragma unroll
            for (int i = 0; i < 4; i++)
                acc[mt][nt][i] = 0.f;

    #pragma unroll 1
    for (int kc = 0; kc < 512 / GBK; kc++) {
        const int k0 = kc * GBK;

        const float* srcA;
        int strideA;
        bool scale = false;
        if (k0 < 128)      { srcA = x      + k0;         strideA = 128; scale = true; }
        else if (k0 < 384) { srcA = g_xacc + (k0 - 128); strideA = 256; }
        else               { srcA = x      + (k0 - 384); strideA = 128; }
        const float* srcB = (k0 < 384) ? (Wmsg + (size_t)k0 * 128)
                                       : (Wself + (size_t)(k0 - 384) * 128);

        __syncthreads();   // previous iteration's compute done before overwrite

        // Load A tile (128 rows x 32 k) -> As[m][k] (tf32-converted)
        {
            const int kq    = (tid & 7) * 4;
            const int mbase = tid >> 3;
            #pragma unroll
            for (int i = 0; i < 4; i++) {
                int m   = mbase + i * 32;
                int row = row0 + m;
                float4 v = make_float4(0.f, 0.f, 0.f, 0.f);
                if (row < N) {
                    v = *(const float4*)(srcA + (size_t)row * strideA + kq);
                    if (scale) {
                        float sc = __ldg(&g_s[row]);
                        v.x *= sc; v.y *= sc; v.z *= sc; v.w *= sc;
                    }
                }
                uint32_t* a = &As[m * A_STRIDE + kq];
                a[0] = f2tf32(v.x); a[1] = f2tf32(v.y);
                a[2] = f2tf32(v.z); a[3] = f2tf32(v.w);
            }
        }
        // Load B tile (32 k x 128 n) -> Bs[k][n] (tf32-converted)
        {
            const int n  = (tid & 31) * 4;
            const int kb = tid >> 5;
            #pragma unroll
            for (int i = 0; i < 4; i++) {
                int k = kb + i * 8;
                float4 v = *(const float4*)(srcB + (size_t)k * 128 + n);
                uint32_t* b = &Bs[k * B_STRIDE + n];
                b[0] = f2tf32(v.x); b[1] = f2tf32(v.y);
                b[2] = f2tf32(v.z); b[3] = f2tf32(v.w);
            }
        }

        __syncthreads();

        #pragma unroll
        for (int ks = 0; ks < 4; ks++) {
            const int kk = ks * 8;
            uint32_t a[4][4];
            #pragma unroll
            for (int mt = 0; mt < 4; mt++) {
                const int mrow = warpM * 64 + mt * 16;
                a[mt][0] = As[(mrow + g)     * A_STRIDE + kk + t];
                a[mt][1] = As[(mrow + 8 + g) * A_STRIDE + kk + t];
                a[mt][2] = As[(mrow + g)     * A_STRIDE + kk + t + 4];
                a[mt][3] = As[(mrow + 8 + g) * A_STRIDE + kk + t + 4];
            }
            uint32_t b[4][2];
            #pragma unroll
            for (int nt = 0; nt < 4; nt++) {
                const int nc = warpN * 32 + nt * 8 + g;
                b[nt][0] = Bs[(kk + t)     * B_STRIDE + nc];
                b[nt][1] = Bs[(kk + t + 4) * B_STRIDE + nc];
            }
            #pragma unroll
            for (int mt = 0; mt < 4; mt++)
                #pragma unroll
                for (int nt = 0; nt < 4; nt++)
                    mma_tf32(acc[mt][nt], a[mt], b[nt]);
        }
    }

    // Epilogue: c0 -> (g, 2t), c1 -> (g, 2t+1), c2/c3 -> rows +8
    #pragma unroll
    for (int mt = 0; mt < 4; mt++) {
        const int r0 = row0 + warpM * 64 + mt * 16 + g;
        const int r1 = r0 + 8;
        #pragma unroll
        for (int nt = 0; nt < 4; nt++) {
            const int c = warpN * 32 + nt * 8 + 2 * t;
            if (r0 < N)
                *(float2*)(out + (size_t)r0 * 128 + c) = make_float2(acc[mt][nt][0], acc[mt][nt][1]);
            if (r1 < N)
                *(float2*)(out + (size_t)r1 * 128 + c) = make_float2(acc[mt][nt][2], acc[mt][nt][3]);
        }
    }
}

// ---------------------------------------------------------------------------
// Launch: CSR build -> gather -> tf32 GEMM (default stream, capturable)
// ---------------------------------------------------------------------------
extern "C" void kernel_launch(void* const* d_in, const int* in_sizes, int n_in,
                              void* d_out, int out_size)
{
    const float* x     = (const float*)d_in[0];
    const int*   eidx  = (const int*)  d_in[1];
    const float* ew    = (const float*)d_in[2];
    const float* ea    = (const float*)d_in[3];
    const float* Wmsg  = (const float*)d_in[4];
    const float* Wself = (const float*)d_in[5];
    float*       out   = (float*)d_out;

    const int E = in_sizes[1] / 2;
    const int N = in_sizes[0] / DIM;
    const int* src = eidx;
    const int* dst = eidx + E;

    const int nScanBlocks = (N + SCAN_B - 1) / SCAN_B;

    zero_counts<<<(N + 255) / 256, 256>>>(N);
    hist_kernel<<<(E + 255) / 256, 256>>>(dst, E);
    scan_block<<<nScanBlocks, SCAN_B>>>(N);
    scan_sums<<<1, 128>>>(nScanBlocks);
    scan_add<<<nScanBlocks, SCAN_B>>>(N);
    scatter_kernel<<<(E + 255) / 256, 256>>>(src, dst, ew, E);

    gather_kernel<<<12544, 256>>>(x, ea, N);

    gemm_tf32_kernel<<<(N + GBM - 1) / GBM, 256>>>(x, Wmsg, Wself, out, N);
}

// round 7
// speedup vs baseline: 1.0674x; 1.0674x over previous
#include <cuda_runtime.h>
#include <cstdint>

// Problem constants (shapes fixed by the dataset)
#define MAX_N 100000
#define MAX_E 640000
#define DIM   128

// Per-node accumulators consumed by the GEMM:
//   g_xacc[n][0:128]   = sum over edges (dst==n) of w_e * x[src_e]
//   g_xacc[n][128:256] = sum over edges (dst==n) of w_e * edge_attr_e
//   g_s[n]             = sum over edges (dst==n) of w_e
__device__ float g_xacc[(size_t)MAX_N * 256];
__device__ float g_s[MAX_N];

// CSR scratch. Triple packed: {src, w_bits, eid, 0} -> one LDG.128 per edge.
__device__ int  g_count[MAX_N];
__device__ int  g_off[MAX_N];
__device__ int  g_cursor[MAX_N];
__device__ int  g_bsum[128];
__device__ int4 g_csr[MAX_E];

// ---------------------------------------------------------------------------
// CSR build: zero counts -> histogram -> exclusive scan -> scatter triples
// ---------------------------------------------------------------------------
__global__ void zero_counts(int N)
{
    int i = blockIdx.x * blockDim.x + threadIdx.x;
    if (i < N) g_count[i] = 0;
}

__global__ void hist_kernel(const int* __restrict__ dst, int E)
{
    int i = blockIdx.x * blockDim.x + threadIdx.x;
    if (i < E) atomicAdd(&g_count[dst[i]], 1);
}

#define SCAN_B 1024
__global__ __launch_bounds__(SCAN_B)
void scan_block(int N)
{
    __shared__ int sh[SCAN_B];
    int i = blockIdx.x * SCAN_B + threadIdx.x;
    int v = (i < N) ? g_count[i] : 0;
    sh[threadIdx.x] = v;
    __syncthreads();
    for (int off = 1; off < SCAN_B; off <<= 1) {
        int t = (threadIdx.x >= off) ? sh[threadIdx.x - off] : 0;
        __syncthreads();
        sh[threadIdx.x] += t;
        __syncthreads();
    }
    int incl = sh[threadIdx.x];
    if (i < N) g_off[i] = incl - v;           // exclusive within block
    if (threadIdx.x == SCAN_B - 1) g_bsum[blockIdx.x] = incl;
}

__global__ __launch_bounds__(128)
void scan_sums(int nb)
{
    __shared__ int sh[128];
    int v = (threadIdx.x < nb) ? g_bsum[threadIdx.x] : 0;
    sh[threadIdx.x] = v;
    __syncthreads();
    for (int off = 1; off < 128; off <<= 1) {
        int t = (threadIdx.x >= off) ? sh[threadIdx.x - off] : 0;
        __syncthreads();
        sh[threadIdx.x] += t;
        __syncthreads();
    }
    if (threadIdx.x < nb) g_bsum[threadIdx.x] = sh[threadIdx.x] - v;  // exclusive
}

__global__ __launch_bounds__(SCAN_B)
void scan_add(int N)
{
    int i = blockIdx.x * SCAN_B + threadIdx.x;
    if (i < N) {
        int o = g_off[i] + g_bsum[blockIdx.x];
        g_off[i]    = o;
        g_cursor[i] = o;
    }
}

__global__ void scatter_kernel(const int* __restrict__ src,
                               const int* __restrict__ dst,
                               const float* __restrict__ ew,
                               int E)
{
    int e = blockIdx.x * blockDim.x + threadIdx.x;
    if (e < E) {
        int d   = dst[e];
        int pos = atomicAdd(&g_cursor[d], 1);
        g_csr[pos] = make_int4(src[e], __float_as_int(ew[e]), e, 0);
    }
}

// ---------------------------------------------------------------------------
// Gather pass: one warp per NODE PAIR. The CSR ranges of nodes 2p and 2p+1
// are contiguous, so the warp streams the combined edge run with an exact
// unroll-4 (no padded/wasted loads) and routes each edge to the right
// accumulator via a warp-uniform weight mask. Mean combined degree ~12.8
// -> ~3 pipelined rounds + short tail (vs 1 round + long tail per node).
// ---------------------------------------------------------------------------
__global__ __launch_bounds__(256)
void gather_kernel(const float* __restrict__ x,
                   const float* __restrict__ ea,
                   int N)
{
    const int lane   = threadIdx.x & 31;
    const int warp0  = (int)((blockIdx.x * blockDim.x + threadIdx.x) >> 5);
    const int nwarps = (int)((gridDim.x * blockDim.x) >> 5);
    const int npairs = (N + 1) >> 1;

    for (int p = warp0; p < npairs; p += nwarps) {
        const int n0   = 2 * p;
        const int n1   = n0 + 1;
        const int deg0 = g_count[n0];
        const int deg1 = (n1 < N) ? g_count[n1] : 0;
        const int start = g_off[n0];
        const int tot   = deg0 + deg1;

        float4 ax0 = make_float4(0.f,0.f,0.f,0.f), aE0 = ax0;
        float4 ax1 = ax0,                           aE1 = ax0;
        float  ws0 = 0.f, ws1 = 0.f;

        int j = 0;
        for (; j + 4 <= tot; j += 4) {
            int4 t0 = __ldg(g_csr + start + j);
            int4 t1 = __ldg(g_csr + start + j + 1);
            int4 t2 = __ldg(g_csr + start + j + 2);
            int4 t3 = __ldg(g_csr + start + j + 3);

            float4 xv0 = __ldg((const float4*)(x + (size_t)t0.x * DIM) + lane);
            float4 xv1 = __ldg((const float4*)(x + (size_t)t1.x * DIM) + lane);
            float4 xv2 = __ldg((const float4*)(x + (size_t)t2.x * DIM) + lane);
            float4 xv3 = __ldg((const float4*)(x + (size_t)t3.x * DIM) + lane);
            float4 ev0 = __ldg((const float4*)(ea + (size_t)t0.z * DIM) + lane);
            float4 ev1 = __ldg((const float4*)(ea + (size_t)t1.z * DIM) + lane);
            float4 ev2 = __ldg((const float4*)(ea + (size_t)t2.z * DIM) + lane);
            float4 ev3 = __ldg((const float4*)(ea + (size_t)t3.z * DIM) + lane);

            float w0 = __int_as_float(t0.y), w1 = __int_as_float(t1.y);
            float w2 = __int_as_float(t2.y), w3 = __int_as_float(t3.y);

            // warp-uniform routing masks
            float a0 = (j     < deg0) ? w0 : 0.f, b0 = w0 - a0;
            float a1 = (j + 1 < deg0) ? w1 : 0.f, b1 = w1 - a1;
            float a2 = (j + 2 < deg0) ? w2 : 0.f, b2 = w2 - a2;
            float a3 = (j + 3 < deg0) ? w3 : 0.f, b3 = w3 - a3;

            ax0.x += a0*xv0.x + a1*xv1.x + a2*xv2.x + a3*xv3.x;
            ax0.y += a0*xv0.y + a1*xv1.y + a2*xv2.y + a3*xv3.y;
            ax0.z += a0*xv0.z + a1*xv1.z + a2*xv2.z + a3*xv3.z;
            ax0.w += a0*xv0.w + a1*xv1.w + a2*xv2.w + a3*xv3.w;
            aE0.x += a0*ev0.x + a1*ev1.x + a2*ev2.x + a3*ev3.x;
            aE0.y += a0*ev0.y + a1*ev1.y + a2*ev2.y + a3*ev3.y;
            aE0.z += a0*ev0.z + a1*ev1.z + a2*ev2.z + a3*ev3.z;
            aE0.w += a0*ev0.w + a1*ev1.w + a2*ev2.w + a3*ev3.w;
            ws0   += (a0 + a1) + (a2 + a3);

            ax1.x += b0*xv0.x + b1*xv1.x + b2*xv2.x + b3*xv3.x;
            ax1.y += b0*xv0.y + b1*xv1.y + b2*xv2.y + b3*xv3.y;
            ax1.z += b0*xv0.z + b1*xv1.z + b2*xv2.z + b3*xv3.z;
            ax1.w += b0*xv0.w + b1*xv1.w + b2*xv2.w + b3*xv3.w;
            aE1.x += b0*ev0.x + b1*ev1.x + b2*ev2.x + b3*ev3.x;
            aE1.y += b0*ev0.y + b1*ev1.y + b2*ev2.y + b3*ev3.y;
            aE1.z += b0*ev0.z + b1*ev1.z + b2*ev2.z + b3*ev3.z;
            aE1.w += b0*ev0.w + b1*ev1.w + b2*ev2.w + b3*ev3.w;
            ws1   += (b0 + b1) + (b2 + b3);
        }
        for (; j < tot; j++) {
            int4  t = __ldg(g_csr + start + j);
            float w = __int_as_float(t.y);
            float4 xv = __ldg((const float4*)(x + (size_t)t.x * DIM) + lane);
            float4 ev = __ldg((const float4*)(ea + (size_t)t.z * DIM) + lane);
            float a = (j < deg0) ? w : 0.f, b = w - a;
            ax0.x += a*xv.x; ax0.y += a*xv.y; ax0.z += a*xv.z; ax0.w += a*xv.w;
            aE0.x += a*ev.x; aE0.y += a*ev.y; aE0.z += a*ev.z; aE0.w += a*ev.w;
            ws0   += a;
            ax1.x += b*xv.x; ax1.y += b*xv.y; ax1.z += b*xv.z; ax1.w += b*xv.w;
            aE1.x += b*ev.x; aE1.y += b*ev.y; aE1.z += b*ev.z; aE1.w += b*ev.w;
            ws1   += b;
        }

        float* base0 = g_xacc + (size_t)n0 * 256 + lane * 4;
        *(float4*)(base0)       = ax0;
        *(float4*)(base0 + 128) = aE0;
        if (lane == 0) g_s[n0] = ws0;
        if (n1 < N) {
            float* base1 = g_xacc + (size_t)n1 * 256 + lane * 4;
            *(float4*)(base1)       = ax1;
            *(float4*)(base1 + 128) = aE1;
            if (lane == 0) g_s[n1] = ws1;
        }
    }
}

// ---------------------------------------------------------------------------
// tf32 tensor-core GEMM:  out[N,128] = A_virtual[N,512] @ Bcat[512,128]
//   A k-regions:   [0,128)  : x * s[row]      (stride 128)
//                  [128,384): g_xacc          (stride 256)
//                  [384,512): x               (stride 128)
//   B k-regions:   [0,384)  : W_msg rows; [384,512): W_self rows
// ---------------------------------------------------------------------------
#define GBM 128
#define GBK 32
#define A_STRIDE 36
#define B_STRIDE 136

__device__ __forceinline__ uint32_t f2tf32(float f)
{
    uint32_t u;
    asm("cvt.rna.tf32.f32 %0, %1;" : "=r"(u) : "f"(f));
    return u;
}

__device__ __forceinline__ void mma_tf32(float c[4], const uint32_t a[4], const uint32_t b[2])
{
    asm("mma.sync.aligned.m16n8k8.row.col.f32.tf32.tf32.f32 "
        "{%0,%1,%2,%3}, {%4,%5,%6,%7}, {%8,%9}, {%0,%1,%2,%3};"
        : "+f"(c[0]), "+f"(c[1]), "+f"(c[2]), "+f"(c[3])
        : "r"(a[0]), "r"(a[1]), "r"(a[2]), "r"(a[3]), "r"(b[0]), "r"(b[1]));
}

__global__ __launch_bounds__(256)
void gemm_tf32_kernel(const float* __restrict__ x,
                      const float* __restrict__ Wmsg,
                      const float* __restrict__ Wself,
                      float* __restrict__ out,
                      int N)
{
    __shared__ uint32_t As[GBM * A_STRIDE];   // [m][k], tf32 bits
    __shared__ uint32_t Bs[GBK * B_STRIDE];   // [k][n], tf32 bits

    const int tid   = threadIdx.x;
    const int lane  = tid & 31;
    const int warp  = tid >> 5;
    const int warpM = warp & 1;     // 0..1
    const int warpN = warp >> 1;    // 0..3
    const int g     = lane >> 2;    // groupID 0..7
    const int t     = lane & 3;     // threadID_in_group 0..3

    const int row0 = blockIdx.x * GBM;

    float acc[4][4][4];
    #pragma unroll
    for (int mt = 0; mt < 4; mt++)
        #pragma unroll
        for (int nt = 0; nt < 4; nt++)
            #pragma unroll
            for (int i = 0; i < 4; i++)
                acc[mt][nt][i] = 0.f;

    #pragma unroll 1
    for (int kc = 0; kc < 512 / GBK; kc++) {
        const int k0 = kc * GBK;

        const float* srcA;
        int strideA;
        bool scale = false;
        if (k0 < 128)      { srcA = x      + k0;         strideA = 128; scale = true; }
        else if (k0 < 384) { srcA = g_xacc + (k0 - 128); strideA = 256; }
        else               { srcA = x      + (k0 - 384); strideA = 128; }
        const float* srcB = (k0 < 384) ? (Wmsg + (size_t)k0 * 128)
                                       : (Wself + (size_t)(k0 - 384) * 128);

        __syncthreads();   // previous iteration's compute done before overwrite

        // Load A tile (128 rows x 32 k) -> As[m][k] (tf32-converted)
        {
            const int kq    = (tid & 7) * 4;
            const int mbase = tid >> 3;
            #pragma unroll
            for (int i = 0; i < 4; i++) {
                int m   = mbase + i * 32;
                int row = row0 + m;
                float4 v = make_float4(0.f, 0.f, 0.f, 0.f);
                if (row < N) {
                    v = *(const float4*)(srcA + (size_t)row * strideA + kq);
                    if (scale) {
                        float sc = __ldg(&g_s[row]);
                        v.x *= sc; v.y *= sc; v.z *= sc; v.w *= sc;
                    }
                }
                uint32_t* a = &As[m * A_STRIDE + kq];
                a[0] = f2tf32(v.x); a[1] = f2tf32(v.y);
                a[2] = f2tf32(v.z); a[3] = f2tf32(v.w);
            }
        }
        // Load B tile (32 k x 128 n) -> Bs[k][n] (tf32-converted)
        {
            const int n  = (tid & 31) * 4;
            const int kb = tid >> 5;
            #pragma unroll
            for (int i = 0; i < 4; i++) {
                int k = kb + i * 8;
                float4 v = *(const float4*)(srcB + (size_t)k * 128 + n);
                uint32_t* b = &Bs[k * B_STRIDE + n];
                b[0] = f2tf32(v.x); b[1] = f2tf32(v.y);
                b[2] = f2tf32(v.z); b[3] = f2tf32(v.w);
            }
        }

        __syncthreads();

        #pragma unroll
        for (int ks = 0; ks < 4; ks++) {
            const int kk = ks * 8;
            uint32_t a[4][4];
            #pragma unroll
            for (int mt = 0; mt < 4; mt++) {
                const int mrow = warpM * 64 + mt * 16;
                a[mt][0] = As[(mrow + g)     * A_STRIDE + kk + t];
                a[mt][1] = As[(mrow + 8 + g) * A_STRIDE + kk + t];
                a[mt][2] = As[(mrow + g)     * A_STRIDE + kk + t + 4];
                a[mt][3] = As[(mrow + 8 + g) * A_STRIDE + kk + t + 4];
            }
            uint32_t b[4][2];
            #pragma unroll
            for (int nt = 0; nt < 4; nt++) {
                const int nc = warpN * 32 + nt * 8 + g;
                b[nt][0] = Bs[(kk + t)     * B_STRIDE + nc];
                b[nt][1] = Bs[(kk + t + 4) * B_STRIDE + nc];
            }
            #pragma unroll
            for (int mt = 0; mt < 4; mt++)
                #pragma unroll
                for (int nt = 0; nt < 4; nt++)
                    mma_tf32(acc[mt][nt], a[mt], b[nt]);
        }
    }

    // Epilogue: c0 -> (g, 2t), c1 -> (g, 2t+1), c2/c3 -> rows +8
    #pragma unroll
    for (int mt = 0; mt < 4; mt++) {
        const int r0 = row0 + warpM * 64 + mt * 16 + g;
        const int r1 = r0 + 8;
        #pragma unroll
        for (int nt = 0; nt < 4; nt++) {
            const int c = warpN * 32 + nt * 8 + 2 * t;
            if (r0 < N)
                *(float2*)(out + (size_t)r0 * 128 + c) = make_float2(acc[mt][nt][0], acc[mt][nt][1]);
            if (r1 < N)
                *(float2*)(out + (size_t)r1 * 128 + c) = make_float2(acc[mt][nt][2], acc[mt][nt][3]);
        }
    }
}

// ---------------------------------------------------------------------------
// Launch: CSR build -> gather -> tf32 GEMM (default stream, capturable)
// ---------------------------------------------------------------------------
extern "C" void kernel_launch(void* const* d_in, const int* in_sizes, int n_in,
                              void* d_out, int out_size)
{
    const float* x     = (const float*)d_in[0];
    const int*   eidx  = (const int*)  d_in[1];
    const float* ew    = (const float*)d_in[2];
    const float* ea    = (const float*)d_in[3];
    const float* Wmsg  = (const float*)d_in[4];
    const float* Wself = (const float*)d_in[5];
    float*       out   = (float*)d_out;

    const int E = in_sizes[1] / 2;
    const int N = in_sizes[0] / DIM;
    const int* src = eidx;
    const int* dst = eidx + E;

    const int nScanBlocks = (N + SCAN_B - 1) / SCAN_B;

    zero_counts<<<(N + 255) / 256, 256>>>(N);
    hist_kernel<<<(E + 255) / 256, 256>>>(dst, E);
    scan_block<<<nScanBlocks, SCAN_B>>>(N);
    scan_sums<<<1, 128>>>(nScanBlocks);
    scan_add<<<nScanBlocks, SCAN_B>>>(N);
    scatter_kernel<<<(E + 255) / 256, 256>>>(src, dst, ew, E);

    gather_kernel<<<12544, 256>>>(x, ea, N);

    gemm_tf32_kernel<<<(N + GBM - 1) / GBM, 256>>>(x, Wmsg, Wself, out, N);
}

// round 8
// speedup vs baseline: 1.3428x; 1.2579x over previous
#include <cuda_runtime.h>
#include <cstdint>

// Problem constants (shapes fixed by the dataset)
#define MAX_N 100000
#define MAX_E 640000
#define DIM   128

// Per-node accumulators consumed by the GEMM:
//   g_xacc[n][0:128]   = sum over edges (dst==n) of w_e * x[src_e]
//   g_xacc[n][128:256] = sum over edges (dst==n) of w_e * edge_attr_e
//   g_s[n]             = sum over edges (dst==n) of w_e
__device__ float g_xacc[(size_t)MAX_N * 256];
__device__ float g_s[MAX_N];

// CSR scratch. Triple packed: {src, w_bits, eid, 0} -> one LDG.128 per edge.
__device__ int  g_count[MAX_N];
__device__ int  g_off[MAX_N];
__device__ int  g_cursor[MAX_N];
__device__ int  g_bsum[128];
__device__ int4 g_csr[MAX_E];

// ---------------------------------------------------------------------------
// CSR build: zero counts -> histogram -> exclusive scan -> scatter triples
// ---------------------------------------------------------------------------
__global__ void zero_counts(int N)
{
    int i = blockIdx.x * blockDim.x + threadIdx.x;
    if (i < N) g_count[i] = 0;
}

__global__ void hist_kernel(const int* __restrict__ dst, int E)
{
    int i = blockIdx.x * blockDim.x + threadIdx.x;
    if (i < E) atomicAdd(&g_count[dst[i]], 1);
}

#define SCAN_B 1024
__global__ __launch_bounds__(SCAN_B)
void scan_block(int N)
{
    __shared__ int sh[SCAN_B];
    int i = blockIdx.x * SCAN_B + threadIdx.x;
    int v = (i < N) ? g_count[i] : 0;
    sh[threadIdx.x] = v;
    __syncthreads();
    for (int off = 1; off < SCAN_B; off <<= 1) {
        int t = (threadIdx.x >= off) ? sh[threadIdx.x - off] : 0;
        __syncthreads();
        sh[threadIdx.x] += t;
        __syncthreads();
    }
    int incl = sh[threadIdx.x];
    if (i < N) g_off[i] = incl - v;           // exclusive within block
    if (threadIdx.x == SCAN_B - 1) g_bsum[blockIdx.x] = incl;
}

__global__ __launch_bounds__(128)
void scan_sums(int nb)
{
    __shared__ int sh[128];
    int v = (threadIdx.x < nb) ? g_bsum[threadIdx.x] : 0;
    sh[threadIdx.x] = v;
    __syncthreads();
    for (int off = 1; off < 128; off <<= 1) {
        int t = (threadIdx.x >= off) ? sh[threadIdx.x - off] : 0;
        __syncthreads();
        sh[threadIdx.x] += t;
        __syncthreads();
    }
    if (threadIdx.x < nb) g_bsum[threadIdx.x] = sh[threadIdx.x] - v;  // exclusive
}

__global__ __launch_bounds__(SCAN_B)
void scan_add(int N)
{
    int i = blockIdx.x * SCAN_B + threadIdx.x;
    if (i < N) {
        int o = g_off[i] + g_bsum[blockIdx.x];
        g_off[i]    = o;
        g_cursor[i] = o;
    }
}

__global__ void scatter_kernel(const int* __restrict__ src,
                               const int* __restrict__ dst,
                               const float* __restrict__ ew,
                               int E)
{
    int e = blockIdx.x * blockDim.x + threadIdx.x;
    if (e < E) {
        int d   = dst[e];
        int pos = atomicAdd(&g_cursor[d], 1);
        g_csr[pos] = make_int4(src[e], __float_as_int(ew[e]), e, 0);
    }
}

// ---------------------------------------------------------------------------
// Gather pass (R5-exact, best known): one warp per node, exact unroll-4.
// ---------------------------------------------------------------------------
__global__ __launch_bounds__(256)
void gather_kernel(const float* __restrict__ x,
                   const float* __restrict__ ea,
                   int N)
{
    const int lane   = threadIdx.x & 31;
    const int warp0  = (int)((blockIdx.x * blockDim.x + threadIdx.x) >> 5);
    const int nwarps = (int)((gridDim.x * blockDim.x) >> 5);

    for (int n = warp0; n < N; n += nwarps) {
        const int start = g_off[n];
        const int deg   = g_count[n];

        float4 ax = make_float4(0.f, 0.f, 0.f, 0.f);
        float4 aE = make_float4(0.f, 0.f, 0.f, 0.f);
        float  ws = 0.f;

        int j = 0;
        for (; j + 4 <= deg; j += 4) {
            int4 t0 = __ldg(g_csr + start + j);
            int4 t1 = __ldg(g_csr + start + j + 1);
            int4 t2 = __ldg(g_csr + start + j + 2);
            int4 t3 = __ldg(g_csr + start + j + 3);

            float4 xv0 = __ldg((const float4*)(x + (size_t)t0.x * DIM) + lane);
            float4 xv1 = __ldg((const float4*)(x + (size_t)t1.x * DIM) + lane);
            float4 xv2 = __ldg((const float4*)(x + (size_t)t2.x * DIM) + lane);
            float4 xv3 = __ldg((const float4*)(x + (size_t)t3.x * DIM) + lane);
            float4 ev0 = __ldg((const float4*)(ea + (size_t)t0.z * DIM) + lane);
            float4 ev1 = __ldg((const float4*)(ea + (size_t)t1.z * DIM) + lane);
            float4 ev2 = __ldg((const float4*)(ea + (size_t)t2.z * DIM) + lane);
            float4 ev3 = __ldg((const float4*)(ea + (size_t)t3.z * DIM) + lane);

            float w0 = __int_as_float(t0.y), w1 = __int_as_float(t1.y);
            float w2 = __int_as_float(t2.y), w3 = __int_as_float(t3.y);

            ax.x += w0*xv0.x + w1*xv1.x; ax.x += w2*xv2.x + w3*xv3.x;
            ax.y += w0*xv0.y + w1*xv1.y; ax.y += w2*xv2.y + w3*xv3.y;
            ax.z += w0*xv0.z + w1*xv1.z; ax.z += w2*xv2.z + w3*xv3.z;
            ax.w += w0*xv0.w + w1*xv1.w; ax.w += w2*xv2.w + w3*xv3.w;
            aE.x += w0*ev0.x + w1*ev1.x; aE.x += w2*ev2.x + w3*ev3.x;
            aE.y += w0*ev0.y + w1*ev1.y; aE.y += w2*ev2.y + w3*ev3.y;
            aE.z += w0*ev0.z + w1*ev1.z; aE.z += w2*ev2.z + w3*ev3.z;
            aE.w += w0*ev0.w + w1*ev1.w; aE.w += w2*ev2.w + w3*ev3.w;
            ws   += (w0 + w1) + (w2 + w3);
        }
        for (; j < deg; j++) {
            int4  t  = __ldg(g_csr + start + j);
            float w  = __int_as_float(t.y);
            float4 xv = __ldg((const float4*)(x + (size_t)t.x * DIM) + lane);
            float4 ev = __ldg((const float4*)(ea + (size_t)t.z * DIM) + lane);
            ax.x += w * xv.x; ax.y += w * xv.y; ax.z += w * xv.z; ax.w += w * xv.w;
            aE.x += w * ev.x; aE.y += w * ev.y; aE.z += w * ev.z; aE.w += w * ev.w;
            ws   += w;
        }

        float* base = g_xacc + (size_t)n * 256 + lane * 4;
        *(float4*)(base)       = ax;
        *(float4*)(base + 128) = aE;
        if (lane == 0) g_s[n] = ws;
    }
}

// ---------------------------------------------------------------------------
// tf32 tensor-core GEMM, 2-stage double-buffered:
//   out[N,128] = A_virtual[N,512] @ Bcat[512,128]
//   A k-regions: [0,128): x*s (stride 128) | [128,384): g_xacc (stride 256)
//                | [384,512): x (stride 128)
//   B k-regions: [0,384): W_msg | [384,512): W_self
// Per iteration: LDG next tile -> MMA current stage -> STS next stage -> sync.
// ---------------------------------------------------------------------------
#define GBM 128
#define GBK 32
#define NKC 16
#define A_STRIDE 36
#define B_STRIDE 136
#define A_TILE_U32 (GBM * A_STRIDE)   // 4608
#define B_TILE_U32 (GBK * B_STRIDE)   // 4352
#define GEMM_SMEM_BYTES ((2 * (A_TILE_U32 + B_TILE_U32)) * 4)   // 71680

__device__ __forceinline__ uint32_t f2tf32(float f)
{
    uint32_t u;
    asm("cvt.rna.tf32.f32 %0, %1;" : "=r"(u) : "f"(f));
    return u;
}

__device__ __forceinline__ void mma_tf32(float c[4], const uint32_t a[4], const uint32_t b[2])
{
    asm("mma.sync.aligned.m16n8k8.row.col.f32.tf32.tf32.f32 "
        "{%0,%1,%2,%3}, {%4,%5,%6,%7}, {%8,%9}, {%0,%1,%2,%3};"
        : "+f"(c[0]), "+f"(c[1]), "+f"(c[2]), "+f"(c[3])
        : "r"(a[0]), "r"(a[1]), "r"(a[2]), "r"(a[3]), "r"(b[0]), "r"(b[1]));
}

__device__ __forceinline__ void ldg_tile(
    int kc, int row0, int N, int tid,
    const float* __restrict__ x,
    const float* __restrict__ Wmsg,
    const float* __restrict__ Wself,
    float4 (&la)[4], float (&ls)[4], bool& scale, float4 (&lb)[4])
{
    const int k0 = kc * GBK;
    const float* srcA;
    int strideA;
    scale = false;
    if (k0 < 128)      { srcA = x      + k0;         strideA = 128; scale = true; }
    else if (k0 < 384) { srcA = g_xacc + (k0 - 128); strideA = 256; }
    else               { srcA = x      + (k0 - 384); strideA = 128; }
    const float* srcB = (k0 < 384) ? (Wmsg + (size_t)k0 * 128)
                                   : (Wself + (size_t)(k0 - 384) * 128);

    const int kq    = (tid & 7) * 4;
    const int mbase = tid >> 3;
    #pragma unroll
    for (int i = 0; i < 4; i++) {
        int row = row0 + mbase + i * 32;
        la[i] = make_float4(0.f, 0.f, 0.f, 0.f);
        ls[i] = 1.f;
        if (row < N) {
            la[i] = *(const float4*)(srcA + (size_t)row * strideA + kq);
            if (scale) ls[i] = __ldg(&g_s[row]);
        }
    }
    const int n  = (tid & 31) * 4;
    const int kb = tid >> 5;
    #pragma unroll
    for (int i = 0; i < 4; i++)
        lb[i] = *(const float4*)(srcB + (size_t)(kb + i * 8) * 128 + n);
}

__device__ __forceinline__ void sts_tile(
    uint32_t* __restrict__ As, uint32_t* __restrict__ Bs, int tid,
    const float4 (&la)[4], const float (&ls)[4], bool scale, const float4 (&lb)[4])
{
    const int kq    = (tid & 7) * 4;
    const int mbase = tid >> 3;
    #pragma unroll
    for (int i = 0; i < 4; i++) {
        const int m  = mbase + i * 32;
        const float sc = scale ? ls[i] : 1.f;
        uint32_t* a = &As[m * A_STRIDE + kq];
        a[0] = f2tf32(la[i].x * sc); a[1] = f2tf32(la[i].y * sc);
        a[2] = f2tf32(la[i].z * sc); a[3] = f2tf32(la[i].w * sc);
    }
    const int n  = (tid & 31) * 4;
    const int kb = tid >> 5;
    #pragma unroll
    for (int i = 0; i < 4; i++) {
        uint32_t* b = &Bs[(kb + i * 8) * B_STRIDE + n];
        b[0] = f2tf32(lb[i].x); b[1] = f2tf32(lb[i].y);
        b[2] = f2tf32(lb[i].z); b[3] = f2tf32(lb[i].w);
    }
}

__global__ __launch_bounds__(256)
void gemm_tf32_kernel(const float* __restrict__ x,
                      const float* __restrict__ Wmsg,
                      const float* __restrict__ Wself,
                      float* __restrict__ out,
                      int N)
{
    extern __shared__ uint32_t smem_u[];
    uint32_t* As = smem_u;                          // [2][A_TILE_U32]
    uint32_t* Bs = smem_u + 2 * A_TILE_U32;         // [2][B_TILE_U32]

    const int tid   = threadIdx.x;
    const int lane  = tid & 31;
    const int warp  = tid >> 5;
    const int warpM = warp & 1;
    const int warpN = warp >> 1;
    const int g     = lane >> 2;
    const int t     = lane & 3;

    const int row0 = blockIdx.x * GBM;

    float acc[4][4][4];
    #pragma unroll
    for (int mt = 0; mt < 4; mt++)
        #pragma unroll
        for (int nt = 0; nt < 4; nt++)
            #pragma unroll
            for (int i = 0; i < 4; i++)
                acc[mt][nt][i] = 0.f;

    float4 la[4], lb[4];
    float  ls[4];
    bool   lscale;

    // Prologue: tile 0 -> stage 0
    ldg_tile(0, row0, N, tid, x, Wmsg, Wself, la, ls, lscale, lb);
    sts_tile(As, Bs, tid, la, ls, lscale, lb);
    __syncthreads();

    #pragma unroll 1
    for (int kc = 0; kc < NKC; kc++) {
        const int cur = kc & 1;
        const int nxt = cur ^ 1;
        uint32_t* Ac = As + cur * A_TILE_U32;
        uint32_t* Bc = Bs + cur * B_TILE_U32;

        // Issue next tile's global loads (overlap with MMA below)
        if (kc + 1 < NKC)
            ldg_tile(kc + 1, row0, N, tid, x, Wmsg, Wself, la, ls, lscale, lb);

        // MMA on current stage
        #pragma unroll
        for (int ks = 0; ks < 4; ks++) {
            const int kk = ks * 8;
            uint32_t a[4][4];
            #pragma unroll
            for (int mt = 0; mt < 4; mt++) {
                const int mrow = warpM * 64 + mt * 16;
                a[mt][0] = Ac[(mrow + g)     * A_STRIDE + kk + t];
                a[mt][1] = Ac[(mrow + 8 + g) * A_STRIDE + kk + t];
                a[mt][2] = Ac[(mrow + g)     * A_STRIDE + kk + t + 4];
                a[mt][3] = Ac[(mrow + 8 + g) * A_STRIDE + kk + t + 4];
            }
            uint32_t b[4][2];
            #pragma unroll
            for (int nt = 0; nt < 4; nt++) {
                const int nc = warpN * 32 + nt * 8 + g;
                b[nt][0] = Bc[(kk + t)     * B_STRIDE + nc];
                b[nt][1] = Bc[(kk + t + 4) * B_STRIDE + nc];
            }
            #pragma unroll
            for (int mt = 0; mt < 4; mt++)
                #pragma unroll
                for (int nt = 0; nt < 4; nt++)
                    mma_tf32(acc[mt][nt], a[mt], b[nt]);
        }

        // Store next tile into the other stage, then sync
        if (kc + 1 < NKC) {
            sts_tile(As + nxt * A_TILE_U32, Bs + nxt * B_TILE_U32,
                     tid, la, ls, lscale, lb);
            __syncthreads();
        }
    }

    // Epilogue: c0 -> (g, 2t), c1 -> (g, 2t+1), c2/c3 -> rows +8
    #pragma unroll
    for (int mt = 0; mt < 4; mt++) {
        const int r0 = row0 + warpM * 64 + mt * 16 + g;
        const int r1 = r0 + 8;
        #pragma unroll
        for (int nt = 0; nt < 4; nt++) {
            const int c = warpN * 32 + nt * 8 + 2 * t;
            if (r0 < N)
                *(float2*)(out + (size_t)r0 * 128 + c) = make_float2(acc[mt][nt][0], acc[mt][nt][1]);
            if (r1 < N)
                *(float2*)(out + (size_t)r1 * 128 + c) = make_float2(acc[mt][nt][2], acc[mt][nt][3]);
        }
    }
}

// ---------------------------------------------------------------------------
// Launch: CSR build -> gather -> tf32 GEMM (default stream, capturable)
// ---------------------------------------------------------------------------
extern "C" void kernel_launch(void* const* d_in, const int* in_sizes, int n_in,
                              void* d_out, int out_size)
{
    const float* x     = (const float*)d_in[0];
    const int*   eidx  = (const int*)  d_in[1];
    const float* ew    = (const float*)d_in[2];
    const float* ea    = (const float*)d_in[3];
    const float* Wmsg  = (const float*)d_in[4];
    const float* Wself = (const float*)d_in[5];
    float*       out   = (float*)d_out;

    const int E = in_sizes[1] / 2;
    const int N = in_sizes[0] / DIM;
    const int* src = eidx;
    const int* dst = eidx + E;

    const int nScanBlocks = (N + SCAN_B - 1) / SCAN_B;

    cudaFuncSetAttribute(gemm_tf32_kernel,
                         cudaFuncAttributeMaxDynamicSharedMemorySize,
                         GEMM_SMEM_BYTES);

    zero_counts<<<(N + 255) / 256, 256>>>(N);
    hist_kernel<<<(E + 255) / 256, 256>>>(dst, E);
    scan_block<<<nScanBlocks, SCAN_B>>>(N);
    scan_sums<<<1, 128>>>(nScanBlocks);
    scan_add<<<nScanBlocks, SCAN_B>>>(N);
    scatter_kernel<<<(E + 255) / 256, 256>>>(src, dst, ew, E);

    gather_kernel<<<12544, 256>>>(x, ea, N);

    gemm_tf32_kernel<<<(N + GBM - 1) / GBM, 256, GEMM_SMEM_BYTES>>>(x, Wmsg, Wself, out, N);
}

// round 9
// speedup vs baseline: 1.3631x; 1.0151x over previous
#include <cuda_runtime.h>
#include <cstdint>

// Problem constants (shapes fixed by the dataset)
#define MAX_N 100000
#define MAX_E 640000
#define DIM   128

// Per-node accumulators consumed by the GEMM:
//   g_xacc[n][0:128]   = sum over edges (dst==n) of w_e * x[src_e]
//   g_xacc[n][128:256] = sum over edges (dst==n) of w_e * edge_attr_e
//   g_s[n]             = sum over edges (dst==n) of w_e
__device__ float g_xacc[(size_t)MAX_N * 256];
__device__ float g_s[MAX_N];

// CSR scratch. Triple packed: {src, w_bits, eid, 0} -> one LDG.128 per edge.
// g_count is zero-initialized statically and re-zeroed by scan_add each run.
__device__ int  g_count[MAX_N];
__device__ int  g_off[MAX_N + 1];
__device__ int  g_cursor[MAX_N];
__device__ int  g_bsum[128];
__device__ int4 g_csr[MAX_E];

// ---------------------------------------------------------------------------
// CSR build (3 launches): histogram -> block scan -> add+finalize -> scatter
// ---------------------------------------------------------------------------
__global__ void hist_kernel(const int* __restrict__ dst, int E)
{
    int i = blockIdx.x * blockDim.x + threadIdx.x;
    if (i < E) atomicAdd(&g_count[dst[i]], 1);
}

#define SCAN_B 1024
__global__ __launch_bounds__(SCAN_B)
void scan_block(int N)
{
    __shared__ int sh[SCAN_B];
    int i = blockIdx.x * SCAN_B + threadIdx.x;
    int v = (i < N) ? g_count[i] : 0;
    sh[threadIdx.x] = v;
    __syncthreads();
    for (int off = 1; off < SCAN_B; off <<= 1) {
        int t = (threadIdx.x >= off) ? sh[threadIdx.x - off] : 0;
        __syncthreads();
        sh[threadIdx.x] += t;
        __syncthreads();
    }
    int incl = sh[threadIdx.x];
    if (i < N) g_off[i] = incl - v;           // exclusive within block
    if (threadIdx.x == SCAN_B - 1) g_bsum[blockIdx.x] = incl;
}

// Adds the cross-block prefix (each block reduces g_bsum itself), initializes
// cursors, writes the off[N]=E sentinel, and RE-ZEROES g_count for the next
// graph replay (hist of the next run needs zeros; scan has consumed them).
__global__ __launch_bounds__(SCAN_B)
void scan_add(int N, int E)
{
    __shared__ int sh[128];
    if (threadIdx.x < 128)
        sh[threadIdx.x] = (threadIdx.x < blockIdx.x) ? g_bsum[threadIdx.x] : 0;
    __syncthreads();
    for (int off = 64; off > 0; off >>= 1) {
        if (threadIdx.x < off) sh[threadIdx.x] += sh[threadIdx.x + off];
        __syncthreads();
    }
    const int prefix = sh[0];

    int i = blockIdx.x * SCAN_B + threadIdx.x;
    if (i < N) {
        int o = g_off[i] + prefix;
        g_off[i]    = o;
        g_cursor[i] = o;
        g_count[i]  = 0;              // pre-zero for next replay
    }
    if (blockIdx.x == 0 && threadIdx.x == 0)
        g_off[N] = E;                 // sentinel: deg[n] = off[n+1]-off[n]
}

__global__ void scatter_kernel(const int* __restrict__ src,
                               const int* __restrict__ dst,
                               const float* __restrict__ ew,
                               int E)
{
    int e = blockIdx.x * blockDim.x + threadIdx.x;
    if (e < E) {
        int d   = dst[e];
        int pos = atomicAdd(&g_cursor[d], 1);
        g_csr[pos] = make_int4(src[e], __float_as_int(ew[e]), e, 0);
    }
}

// ---------------------------------------------------------------------------
// Gather pass (R5-exact, best known): one warp per node, exact unroll-4.
// Degree read as off[n+1]-off[n].
// ---------------------------------------------------------------------------
__global__ __launch_bounds__(256)
void gather_kernel(const float* __restrict__ x,
                   const float* __restrict__ ea,
                   int N)
{
    const int lane   = threadIdx.x & 31;
    const int warp0  = (int)((blockIdx.x * blockDim.x + threadIdx.x) >> 5);
    const int nwarps = (int)((gridDim.x * blockDim.x) >> 5);

    for (int n = warp0; n < N; n += nwarps) {
        const int start = g_off[n];
        const int deg   = g_off[n + 1] - start;

        float4 ax = make_float4(0.f, 0.f, 0.f, 0.f);
        float4 aE = make_float4(0.f, 0.f, 0.f, 0.f);
        float  ws = 0.f;

        int j = 0;
        for (; j + 4 <= deg; j += 4) {
            int4 t0 = __ldg(g_csr + start + j);
            int4 t1 = __ldg(g_csr + start + j + 1);
            int4 t2 = __ldg(g_csr + start + j + 2);
            int4 t3 = __ldg(g_csr + start + j + 3);

            float4 xv0 = __ldg((const float4*)(x + (size_t)t0.x * DIM) + lane);
            float4 xv1 = __ldg((const float4*)(x + (size_t)t1.x * DIM) + lane);
            float4 xv2 = __ldg((const float4*)(x + (size_t)t2.x * DIM) + lane);
            float4 xv3 = __ldg((const float4*)(x + (size_t)t3.x * DIM) + lane);
            float4 ev0 = __ldg((const float4*)(ea + (size_t)t0.z * DIM) + lane);
            float4 ev1 = __ldg((const float4*)(ea + (size_t)t1.z * DIM) + lane);
            float4 ev2 = __ldg((const float4*)(ea + (size_t)t2.z * DIM) + lane);
            float4 ev3 = __ldg((const float4*)(ea + (size_t)t3.z * DIM) + lane);

            float w0 = __int_as_float(t0.y), w1 = __int_as_float(t1.y);
            float w2 = __int_as_float(t2.y), w3 = __int_as_float(t3.y);

            ax.x += w0*xv0.x + w1*xv1.x; ax.x += w2*xv2.x + w3*xv3.x;
            ax.y += w0*xv0.y + w1*xv1.y; ax.y += w2*xv2.y + w3*xv3.y;
            ax.z += w0*xv0.z + w1*xv1.z; ax.z += w2*xv2.z + w3*xv3.z;
            ax.w += w0*xv0.w + w1*xv1.w; ax.w += w2*xv2.w + w3*xv3.w;
            aE.x += w0*ev0.x + w1*ev1.x; aE.x += w2*ev2.x + w3*ev3.x;
            aE.y += w0*ev0.y + w1*ev1.y; aE.y += w2*ev2.y + w3*ev3.y;
            aE.z += w0*ev0.z + w1*ev1.z; aE.z += w2*ev2.z + w3*ev3.z;
            aE.w += w0*ev0.w + w1*ev1.w; aE.w += w2*ev2.w + w3*ev3.w;
            ws   += (w0 + w1) + (w2 + w3);
        }
        for (; j < deg; j++) {
            int4  t  = __ldg(g_csr + start + j);
            float w  = __int_as_float(t.y);
            float4 xv = __ldg((const float4*)(x + (size_t)t.x * DIM) + lane);
            float4 ev = __ldg((const float4*)(ea + (size_t)t.z * DIM) + lane);
            ax.x += w * xv.x; ax.y += w * xv.y; ax.z += w * xv.z; ax.w += w * xv.w;
            aE.x += w * ev.x; aE.y += w * ev.y; aE.z += w * ev.z; aE.w += w * ev.w;
            ws   += w;
        }

        float* base = g_xacc + (size_t)n * 256 + lane * 4;
        *(float4*)(base)       = ax;
        *(float4*)(base + 128) = aE;
        if (lane == 0) g_s[n] = ws;
    }
}

// ---------------------------------------------------------------------------
// tf32 tensor-core GEMM, 2-stage double-buffered (R8-exact):
//   out[N,128] = A_virtual[N,512] @ Bcat[512,128]
//   A k-regions: [0,128): x*s (stride 128) | [128,384): g_xacc (stride 256)
//                | [384,512): x (stride 128)
//   B k-regions: [0,384): W_msg | [384,512): W_self
// Per iteration: LDG next tile -> MMA current stage -> STS next stage -> sync.
// ---------------------------------------------------------------------------
#define GBM 128
#define GBK 32
#define NKC 16
#define A_STRIDE 36
#define B_STRIDE 136
#define A_TILE_U32 (GBM * A_STRIDE)   // 4608
#define B_TILE_U32 (GBK * B_STRIDE)   // 4352
#define GEMM_SMEM_BYTES ((2 * (A_TILE_U32 + B_TILE_U32)) * 4)   // 71680

__device__ __forceinline__ uint32_t f2tf32(float f)
{
    uint32_t u;
    asm("cvt.rna.tf32.f32 %0, %1;" : "=r"(u) : "f"(f));
    return u;
}

__device__ __forceinline__ void mma_tf32(float c[4], const uint32_t a[4], const uint32_t b[2])
{
    asm("mma.sync.aligned.m16n8k8.row.col.f32.tf32.tf32.f32 "
        "{%0,%1,%2,%3}, {%4,%5,%6,%7}, {%8,%9}, {%0,%1,%2,%3};"
        : "+f"(c[0]), "+f"(c[1]), "+f"(c[2]), "+f"(c[3])
        : "r"(a[0]), "r"(a[1]), "r"(a[2]), "r"(a[3]), "r"(b[0]), "r"(b[1]));
}

__device__ __forceinline__ void ldg_tile(
    int kc, int row0, int N, int tid,
    const float* __restrict__ x,
    const float* __restrict__ Wmsg,
    const float* __restrict__ Wself,
    float4 (&la)[4], float (&ls)[4], bool& scale, float4 (&lb)[4])
{
    const int k0 = kc * GBK;
    const float* srcA;
    int strideA;
    scale = false;
    if (k0 < 128)      { srcA = x      + k0;         strideA = 128; scale = true; }
    else if (k0 < 384) { srcA = g_xacc + (k0 - 128); strideA = 256; }
    else               { srcA = x      + (k0 - 384); strideA = 128; }
    const float* srcB = (k0 < 384) ? (Wmsg + (size_t)k0 * 128)
                                   : (Wself + (size_t)(k0 - 384) * 128);

    const int kq    = (tid & 7) * 4;
    const int mbase = tid >> 3;
    #pragma unroll
    for (int i = 0; i < 4; i++) {
        int row = row0 + mbase + i * 32;
        la[i] = make_float4(0.f, 0.f, 0.f, 0.f);
        ls[i] = 1.f;
        if (row < N) {
            la[i] = *(const float4*)(srcA + (size_t)row * strideA + kq);
            if (scale) ls[i] = __ldg(&g_s[row]);
        }
    }
    const int n  = (tid & 31) * 4;
    const int kb = tid >> 5;
    #pragma unroll
    for (int i = 0; i < 4; i++)
        lb[i] = *(const float4*)(srcB + (size_t)(kb + i * 8) * 128 + n);
}

__device__ __forceinline__ void sts_tile(
    uint32_t* __restrict__ As, uint32_t* __restrict__ Bs, int tid,
    const float4 (&la)[4], const float (&ls)[4], bool scale, const float4 (&lb)[4])
{
    const int kq    = (tid & 7) * 4;
    const int mbase = tid >> 3;
    #pragma unroll
    for (int i = 0; i < 4; i++) {
        const int m  = mbase + i * 32;
        const float sc = scale ? ls[i] : 1.f;
        uint32_t* a = &As[m * A_STRIDE + kq];
        a[0] = f2tf32(la[i].x * sc); a[1] = f2tf32(la[i].y * sc);
        a[2] = f2tf32(la[i].z * sc); a[3] = f2tf32(la[i].w * sc);
    }
    const int n  = (tid & 31) * 4;
    const int kb = tid >> 5;
    #pragma unroll
    for (int i = 0; i < 4; i++) {
        uint32_t* b = &Bs[(kb + i * 8) * B_STRIDE + n];
        b[0] = f2tf32(lb[i].x); b[1] = f2tf32(lb[i].y);
        b[2] = f2tf32(lb[i].z); b[3] = f2tf32(lb[i].w);
    }
}

__global__ __launch_bounds__(256)
void gemm_tf32_kernel(const float* __restrict__ x,
                      const float* __restrict__ Wmsg,
                      const float* __restrict__ Wself,
                      float* __restrict__ out,
                      int N)
{
    extern __shared__ uint32_t smem_u[];
    uint32_t* As = smem_u;                          // [2][A_TILE_U32]
    uint32_t* Bs = smem_u + 2 * A_TILE_U32;         // [2][B_TILE_U32]

    const int tid   = threadIdx.x;
    const int lane  = tid & 31;
    const int warp  = tid >> 5;
    const int warpM = warp & 1;
    const int warpN = warp >> 1;
    const int g     = lane >> 2;
    const int t     = lane & 3;

    const int row0 = blockIdx.x * GBM;

    float acc[4][4][4];
    #pragma unroll
    for (int mt = 0; mt < 4; mt++)
        #pragma unroll
        for (int nt = 0; nt < 4; nt++)
            #pragma unroll
            for (int i = 0; i < 4; i++)
                acc[mt][nt][i] = 0.f;

    float4 la[4], lb[4];
    float  ls[4];
    bool   lscale;

    // Prologue: tile 0 -> stage 0
    ldg_tile(0, row0, N, tid, x, Wmsg, Wself, la, ls, lscale, lb);
    sts_tile(As, Bs, tid, la, ls, lscale, lb);
    __syncthreads();

    #pragma unroll 1
    for (int kc = 0; kc < NKC; kc++) {
        const int cur = kc & 1;
        const int nxt = cur ^ 1;
        uint32_t* Ac = As + cur * A_TILE_U32;
        uint32_t* Bc = Bs + cur * B_TILE_U32;

        // Issue next tile's global loads (overlap with MMA below)
        if (kc + 1 < NKC)
            ldg_tile(kc + 1, row0, N, tid, x, Wmsg, Wself, la, ls, lscale, lb);

        // MMA on current stage
        #pragma unroll
        for (int ks = 0; ks < 4; ks++) {
            const int kk = ks * 8;
            uint32_t a[4][4];
            #pragma unroll
            for (int mt = 0; mt < 4; mt++) {
                const int mrow = warpM * 64 + mt * 16;
                a[mt][0] = Ac[(mrow + g)     * A_STRIDE + kk + t];
                a[mt][1] = Ac[(mrow + 8 + g) * A_STRIDE + kk + t];
                a[mt][2] = Ac[(mrow + g)     * A_STRIDE + kk + t + 4];
                a[mt][3] = Ac[(mrow + 8 + g) * A_STRIDE + kk + t + 4];
            }
            uint32_t b[4][2];
            #pragma unroll
            for (int nt = 0; nt < 4; nt++) {
                const int nc = warpN * 32 + nt * 8 + g;
                b[nt][0] = Bc[(kk + t)     * B_STRIDE + nc];
                b[nt][1] = Bc[(kk + t + 4) * B_STRIDE + nc];
            }
            #pragma unroll
            for (int mt = 0; mt < 4; mt++)
                #pragma unroll
                for (int nt = 0; nt < 4; nt++)
                    mma_tf32(acc[mt][nt], a[mt], b[nt]);
        }

        // Store next tile into the other stage, then sync
        if (kc + 1 < NKC) {
            sts_tile(As + nxt * A_TILE_U32, Bs + nxt * B_TILE_U32,
                     tid, la, ls, lscale, lb);
            __syncthreads();
        }
    }

    // Epilogue: c0 -> (g, 2t), c1 -> (g, 2t+1), c2/c3 -> rows +8
    #pragma unroll
    for (int mt = 0; mt < 4; mt++) {
        const int r0 = row0 + warpM * 64 + mt * 16 + g;
        const int r1 = r0 + 8;
        #pragma unroll
        for (int nt = 0; nt < 4; nt++) {
            const int c = warpN * 32 + nt * 8 + 2 * t;
            if (r0 < N)
                *(float2*)(out + (size_t)r0 * 128 + c) = make_float2(acc[mt][nt][0], acc[mt][nt][1]);
            if (r1 < N)
                *(float2*)(out + (size_t)r1 * 128 + c) = make_float2(acc[mt][nt][2], acc[mt][nt][3]);
        }
    }
}

// ---------------------------------------------------------------------------
// Launch: CSR build (3 launches) -> gather -> tf32 GEMM (capturable)
// ---------------------------------------------------------------------------
extern "C" void kernel_launch(void* const* d_in, const int* in_sizes, int n_in,
                              void* d_out, int out_size)
{
    const float* x     = (const float*)d_in[0];
    const int*   eidx  = (const int*)  d_in[1];
    const float* ew    = (const float*)d_in[2];
    const float* ea    = (const float*)d_in[3];
    const float* Wmsg  = (const float*)d_in[4];
    const float* Wself = (const float*)d_in[5];
    float*       out   = (float*)d_out;

    const int E = in_sizes[1] / 2;
    const int N = in_sizes[0] / DIM;
    const int* src = eidx;
    const int* dst = eidx + E;

    const int nScanBlocks = (N + SCAN_B - 1) / SCAN_B;

    cudaFuncSetAttribute(gemm_tf32_kernel,
                         cudaFuncAttributeMaxDynamicSharedMemorySize,
                         GEMM_SMEM_BYTES);

    hist_kernel<<<(E + 255) / 256, 256>>>(dst, E);
    scan_block<<<nScanBlocks, SCAN_B>>>(N);
    scan_add<<<nScanBlocks, SCAN_B>>>(N, E);
    scatter_kernel<<<(E + 255) / 256, 256>>>(src, dst, ew, E);

    gather_kernel<<<12544, 256>>>(x, ea, N);

    gemm_tf32_kernel<<<(N + GBM - 1) / GBM, 256, GEMM_SMEM_BYTES>>>(x, Wmsg, Wself, out, N);
}